// round 16
// baseline (speedup 1.0000x reference)
#include <cuda_runtime.h>
#include <cstdint>

#define TT 1024
#define DD 64
#define HH 256
#define OO 128
#define THREADS 512

typedef unsigned long long ull;

// smem float offsets (dynamic, 86080 B) — duplicated h/x layout
#define OFF_WX1 0        // [64][32] ull pairs (wA,wB) per k per lane
#define OFF_H1  4096     // [2][2048] h1dup[p][(col*4+m)*2]  (each value duplicated)
#define OFF_H2  8192     // [2][2048]
#define OFF_XT  12288    // [2][512]  xdup[p][(k*4+m)*2]
#define OFF_SCRA 13312   // [16][256] layer-1 reduction scratch
#define OFF_SCRB 17408   // [16][256] layer-2 reduction scratch
#define OFF_MBAR 21504   // 8 x u64 mbarriers
#define SMEM_FLOATS 21520
#define SMEM_BYTES (SMEM_FLOATS * 4)
#define MB1_B (OFF_MBAR * 4)          // mb1[s] = MB1_B + 8*s  (h1, per source)
#define MB2_B (OFF_MBAR * 4 + 32)     // mb2[s] = MB2_B + 8*s  (h2, per source)

__device__ __forceinline__ ull ffma2(ull a, ull b, ull c) {
    ull d; asm("fma.rn.f32x2 %0,%1,%2,%3;" : "=l"(d) : "l"(a), "l"(b), "l"(c)); return d;
}
__device__ __forceinline__ ull pk2(float lo, float hi) {
    ull d; asm("mov.b64 %0,{%1,%2};" : "=l"(d) : "f"(lo), "f"(hi)); return d;
}
__device__ __forceinline__ void up2(ull a, float& lo, float& hi) {
    asm("mov.b64 {%0,%1},%2;" : "=f"(lo), "=f"(hi) : "l"(a));
}
__device__ __forceinline__ uint32_t s2u(const void* p) {
    uint32_t a;
    asm("{.reg .u64 t; cvta.to.shared.u64 t, %1; cvt.u32.u64 %0, t;}" : "=r"(a) : "l"(p));
    return a;
}
__device__ __forceinline__ void mbar_init(uint32_t m, uint32_t cnt) {
    asm volatile("mbarrier.init.shared.b64 [%0], %1;" :: "r"(m), "r"(cnt) : "memory");
}
__device__ __forceinline__ void mbar_expect(uint32_t m, uint32_t bytes) {
    asm volatile("mbarrier.arrive.expect_tx.shared.b64 _, [%0], %1;" :: "r"(m), "r"(bytes) : "memory");
}
__device__ __forceinline__ void mbar_wait(uint32_t m, uint32_t parity) {
    asm volatile(
        "{\n\t.reg .pred P;\n"
        "W%=:\n\t"
        "mbarrier.try_wait.parity.acquire.cta.shared::cta.b64 P, [%0], %1, 0x989680;\n\t"
        "@!P bra W%=;\n\t}"
        :: "r"(m), "r"(parity) : "memory");
}
__device__ __forceinline__ void st_async_f32(uint32_t daddr, float v, uint32_t dmbar) {
    asm volatile("st.async.shared::cluster.mbarrier::complete_tx::bytes.f32 [%0], %1, [%2];"
                 :: "r"(daddr), "f"(v), "r"(dmbar) : "memory");
}
#define CLUSTER_SYNC() do { \
    asm volatile("barrier.cluster.arrive.aligned;" ::: "memory"); \
    asm volatile("barrier.cluster.wait.aligned;" ::: "memory"); } while (0)

// fast tanh: (e^{2x}-1)/(e^{2x}+1) via MUFU ex2/rcp. Correct limits at +-inf.
__device__ __forceinline__ float ftanh(float x) {
    float e = __expf(2.f * x);
    return 1.f - 2.f * __fdividef(1.f, e + 1.f);
}

// 16 k-steps vs packed (wA,wB) register weights against duplicated h.
// hv = float4 view of hdup rows for this warp (2 float4 per k). Zero MOVs.
__device__ __forceinline__ void accum16(const ull (&wp)[16], const float4* __restrict__ hv,
                                        ull& a0, ull& a1, ull& a2, ull& a3) {
#pragma unroll
    for (int i = 0; i < 16; i++) {
        float4 u = hv[2 * i];          // (h_m0,h_m0,h_m1,h_m1)
        float4 v = hv[2 * i + 1];      // (h_m2,h_m2,h_m3,h_m3)
        a0 = ffma2(wp[i], pk2(u.x, u.y), a0);
        a1 = ffma2(wp[i], pk2(u.z, u.w), a1);
        a2 = ffma2(wp[i], pk2(v.x, v.y), a2);
        a3 = ffma2(wp[i], pk2(v.z, v.w), a3);
    }
}

// 4 k-steps of x-projection; packed weights from smem, duplicated x.
__device__ __forceinline__ void accum_x(const ull* __restrict__ wxp, int w, int lane,
                                        const float4* __restrict__ xv,
                                        ull& a0, ull& a1, ull& a2, ull& a3) {
#pragma unroll
    for (int i = 0; i < 4; i++) {
        int k = 4 * w + i;
        ull w2 = wxp[k * 32 + lane];
        float4 u = xv[2 * k];
        float4 v = xv[2 * k + 1];
        a0 = ffma2(w2, pk2(u.x, u.y), a0);
        a1 = ffma2(w2, pk2(u.z, u.w), a1);
        a2 = ffma2(w2, pk2(v.x, v.y), a2);
        a3 = ffma2(w2, pk2(v.z, v.w), a3);
    }
}

// ONE-bar 16-way reduce (phase-owned scratch) + tree-sum + bias + ftanh +
// duplicated-pair f32 st.async broadcast completing PER-SOURCE mbarriers.
__device__ __forceinline__ void reduce_bcast(float* sm, int tid, int w, int lane,
                                             ull a0, ull a1, ull a2, ull a3,
                                             float bias, int scr, int dst_off, int colg,
                                             const uint32_t (&peer)[4], uint32_t mbar_src_b) {
    // acc_m = (colA,colB) pair; regroup into per-column float4 partials
    float a0l, a0h, a1l, a1h, a2l, a2h, a3l, a3h;
    up2(a0, a0l, a0h); up2(a1, a1l, a1h);
    up2(a2, a2l, a2h); up2(a3, a3l, a3h);
    float4* base = (float4*)(sm + scr + w * 256 + 8 * lane);
    base[0] = make_float4(a0l, a1l, a2l, a3l);   // colA m0..3
    base[1] = make_float4(a0h, a1h, a2h, a3h);   // colB m0..3
    __syncthreads();                             // single bar: partials visible
    if (tid < 256) {
        const float* s0 = sm + scr + tid;
        float t0 = s0[0 * 256] + s0[8 * 256];
        float t1 = s0[1 * 256] + s0[9 * 256];
        float t2 = s0[2 * 256] + s0[10 * 256];
        float t3 = s0[3 * 256] + s0[11 * 256];
        float t4 = s0[4 * 256] + s0[12 * 256];
        float t5 = s0[5 * 256] + s0[13 * 256];
        float t6 = s0[6 * 256] + s0[14 * 256];
        float t7 = s0[7 * 256] + s0[15 * 256];
        t0 += t4; t1 += t5; t2 += t6; t3 += t7;
        float h = ftanh(((t0 + t2) + (t1 + t3)) + bias);
        // duplicated layout: pair at (colg*4 + tid)*2 floats
        uint32_t off = (uint32_t)(dst_off + (colg * 4 + tid) * 2) * 4u;
#pragma unroll
        for (int r = 0; r < 4; r++) {
            st_async_f32(peer[r] + off, h, peer[r] + mbar_src_b);
            st_async_f32(peer[r] + off + 4u, h, peer[r] + mbar_src_b);
        }
    }
}

__global__ void __launch_bounds__(THREADS, 1) __cluster_dims__(4, 1, 1)
rnn_kernel(const float* __restrict__ x, const float* __restrict__ Wx1,
           const float* __restrict__ Wh1, const float* __restrict__ b1,
           const float* __restrict__ Wx2, const float* __restrict__ Wh2,
           const float* __restrict__ b2, const float* __restrict__ Wd,
           const float* __restrict__ bd, float* __restrict__ out) {
    extern __shared__ float sm[];
    int tid = threadIdx.x;
    int w = tid >> 5, lane = tid & 31;
    uint32_t rank;
    asm("mov.u32 %0, %%cluster_ctarank;" : "=r"(rank));
    int colg = (int)rank * 64;
    int bm0 = ((int)blockIdx.x >> 2) * 4;
    uint32_t src8 = 8u * (uint32_t)(w >> 2);        // this warp's h-source CTA * 8
    bool owner = ((w & 3) == 0) && (lane == 0);     // one poster per source barrier

    // Wx1 slice -> smem as packed (wA,wB) ull pairs [64 k][32 lane]
    {
        ull* wxp = (ull*)(sm + OFF_WX1);
        const float2* gx = (const float2*)Wx1;
        for (int i = tid; i < 64 * 32; i += THREADS) {
            int k = i >> 5, l = i & 31;
            float2 v = gx[k * (HH / 2) + (colg >> 1) + l];
            wxp[k * 32 + l] = pk2(v.x, v.y);
        }
    }
    // zero h1dup + h2dup + xdup (contiguous 4096..13312)
    for (int i = tid; i < 9216; i += THREADS) sm[OFF_H1 + i] = 0.f;

    // recurrent weights -> packed (wA,wB) ull registers: warp w owns
    // k in [16w,16w+16), lane owns cols {colg+2*lane, colg+2*lane+1}
    ull wh1p[16], wx2p[16], wh2p[16];
    {
        const float2* g1 = (const float2*)Wh1;
        const float2* g2 = (const float2*)Wx2;
        const float2* g3 = (const float2*)Wh2;
        int cw = (colg >> 1) + lane;
#pragma unroll
        for (int i = 0; i < 16; i++) {
            float2 a = g1[(16 * w + i) * (HH / 2) + cw]; wh1p[i] = pk2(a.x, a.y);
            float2 b = g2[(16 * w + i) * (HH / 2) + cw]; wx2p[i] = pk2(b.x, b.y);
            float2 c = g3[(16 * w + i) * (HH / 2) + cw]; wh2p[i] = pk2(c.x, c.y);
        }
    }
    float b1v = 0.f, b2v = 0.f;
    if (tid < 256) {
        b1v = b1[colg + (tid >> 2)];
        b2v = b2[colg + (tid >> 2)];
    }
    uint32_t su = s2u(sm);
    uint32_t peer[4];
#pragma unroll
    for (int r = 0; r < 4; r++)
        asm("mapa.shared::cluster.u32 %0,%1,%2;" : "=r"(peer[r]) : "r"(su), "r"(r));

    if (tid == 0) {
#pragma unroll
        for (int s = 0; s < 4; s++) {
            mbar_init(su + MB1_B + 8 * s, 1);
            mbar_init(su + MB2_B + 8 * s, 1);
        }
#pragma unroll
        for (int s = 0; s < 4; s++) {          // phase-0 expects (2 KB per source)
            mbar_expect(su + MB1_B + 8 * s, 2048);
            mbar_expect(su + MB2_B + 8 * s, 2048);
        }
    }
    // stage x(0) duplicated: xdup[0][(k*4+m)*2]
    const size_t xbase = (size_t)(bm0 + (tid & 3)) * TT * DD + (tid >> 2);
    if (tid < 256) {
        float v = x[xbase];
        ((float2*)(sm + OFF_XT))[tid] = make_float2(v, v);
    }
    __syncthreads();
    CLUSTER_SYNC();   // mbarriers + expects + buffers live before any st.async

    // initial L1(0) partials (h1(-1) = zeros in parity-1 buffer)
    ull a0 = 0, a1 = 0, a2 = 0, a3 = 0;
    accum_x((const ull*)(sm + OFF_WX1), w, lane, (const float4*)(sm + OFF_XT), a0, a1, a2, a3);
    accum16(wh1p, (const float4*)(sm + OFF_H1 + 2048) + 32 * w, a0, a1, a2, a3);

#pragma unroll 1
    for (int t = 0; t < TT; t++) {
        int p = t & 1, pn = p ^ 1;
        // ---- phase A: finish layer 1, broadcast h1(t) ----
        reduce_bcast(sm, tid, w, lane, a0, a1, a2, a3, b1v,
                     OFF_SCRA, OFF_H1 + p * 2048, colg, peer, MB1_B + 8 * rank);
        // per-warp wait: only this warp's h2 source slice (skip at t=0: zeros)
        if (t) {
            mbar_wait(su + MB2_B + src8, (uint32_t)((t - 1) & 1));
            if (owner) mbar_expect(su + MB2_B + src8, 2048);   // next phase, now safe
        }
        a0 = 0; a1 = 0; a2 = 0; a3 = 0;
        accum16(wh2p, (const float4*)(sm + OFF_H2 + pn * 2048) + 32 * w, a0, a1, a2, a3);
        if (t + 1 < TT && tid < 256) {
            float v = x[xbase + (size_t)(t + 1) * DD];
            ((float2*)(sm + OFF_XT + pn * 512))[tid] = make_float2(v, v);
        }

        // ---- phase B: Wx2*h1(t), finish layer 2, broadcast h2(t) ----
        mbar_wait(su + MB1_B + src8, (uint32_t)p);   // this warp's h1 source slice
        if (owner) mbar_expect(su + MB1_B + src8, 2048);       // next phase, now safe
        accum16(wx2p, (const float4*)(sm + OFF_H1 + p * 2048) + 32 * w, a0, a1, a2, a3);
        reduce_bcast(sm, tid, w, lane, a0, a1, a2, a3, b2v,
                     OFF_SCRB, OFF_H2 + p * 2048, colg, peer, MB2_B + 8 * rank);
        // hidden: L1(t+1) = Wx1*x(t+1) + Wh1*h1(t)  (h1 src already waited)
        a0 = 0; a1 = 0; a2 = 0; a3 = 0;
        if (t + 1 < TT) {
            accum_x((const ull*)(sm + OFF_WX1), w, lane,
                    (const float4*)(sm + OFF_XT + pn * 512), a0, a1, a2, a3);
            accum16(wh1p, (const float4*)(sm + OFF_H1 + p * 2048) + 32 * w, a0, a1, a2, a3);
        }
    }
    // make final h2 (all 4 source slices, step-1023 phase parity = 1) visible
#pragma unroll
    for (int s = 0; s < 4; s++) mbar_wait(su + MB2_B + 8 * s, 1u);
    __syncthreads();

    // ---- epilogue: every rank outputs its own batch row (h2 replicated) ----
    {
        const float* h2f = sm + OFF_H2 + 2048;  // parity of t=1023 is 1 (dup layout)
        int kq = tid >> 7, o = tid & 127;
        float part = 0.f;
#pragma unroll 8
        for (int i = 0; i < 64; i++) {
            int k = kq * 64 + i;
            part += h2f[(k * 4 + (int)rank) * 2] * Wd[k * OO + o];
        }
        sm[OFF_SCRA + kq * 128 + o] = part;
        __syncthreads();
        if (tid < 128) {
            float l = bd[tid] + sm[OFF_SCRA + tid] + sm[OFF_SCRA + 128 + tid]
                    + sm[OFF_SCRA + 256 + tid] + sm[OFF_SCRA + 384 + tid];
            sm[OFF_SCRA + 512 + tid] = l;
        }
        __syncthreads();
        if (tid < 32) {
            const float* L = sm + OFF_SCRA + 512;
            float v0 = L[tid], v1 = L[tid + 32], v2 = L[tid + 64], v3 = L[tid + 96];
            float mx = fmaxf(fmaxf(v0, v1), fmaxf(v2, v3));
#pragma unroll
            for (int s = 16; s; s >>= 1) mx = fmaxf(mx, __shfl_xor_sync(0xffffffffu, mx, s));
            float e0 = __expf(v0 - mx), e1 = __expf(v1 - mx);
            float e2 = __expf(v2 - mx), e3 = __expf(v3 - mx);
            float ssum = e0 + e1 + e2 + e3;
#pragma unroll
            for (int s = 16; s; s >>= 1) ssum += __shfl_xor_sync(0xffffffffu, ssum, s);
            float inv = 1.f / ssum;
            float* orow = out + (size_t)(bm0 + (int)rank) * OO;
            orow[tid] = e0 * inv;
            orow[tid + 32] = e1 * inv;
            orow[tid + 64] = e2 * inv;
            orow[tid + 96] = e3 * inv;
        }
    }
    CLUSTER_SYNC();   // keep cluster alive until all in-flight st.async land
}

extern "C" void kernel_launch(void* const* d_in, const int* in_sizes, int n_in,
                              void* d_out, int out_size) {
    cudaFuncSetAttribute(rnn_kernel, cudaFuncAttributeMaxDynamicSharedMemorySize, SMEM_BYTES);
    rnn_kernel<<<128, THREADS, SMEM_BYTES>>>(
        (const float*)d_in[0], (const float*)d_in[1], (const float*)d_in[2],
        (const float*)d_in[3], (const float*)d_in[4], (const float*)d_in[5],
        (const float*)d_in[6], (const float*)d_in[7], (const float*)d_in[8],
        (float*)d_out);
}